// round 2
// baseline (speedup 1.0000x reference)
#include <cuda_runtime.h>
#include <math.h>

#define NROWS 8192
#define FIN   512
#define FOUT  64
#define ALPHA 0.2f

// Scratch (no cudaMalloc allowed)
__device__ float g_h[NROWS * FOUT];   // h = x @ W
__device__ float g_a1[NROWS];
__device__ float g_a2[NROWS];
__device__ float g_a2max;

// ---------------------------------------------------------------------------
// K1: h = x @ W   (8192x512 @ 512x64), FP32, 64x64 CTA tile, 4x4 per thread
// ---------------------------------------------------------------------------
__global__ __launch_bounds__(256) void k1_gemm(const float* __restrict__ x,
                                               const float* __restrict__ W) {
    __shared__ __align__(16) float xT[32][68];  // [k][row]
    __shared__ __align__(16) float Ws[32][68];  // [k][col]
    const int tid = threadIdx.x;
    const int ty = tid >> 4, tx = tid & 15;
    const int row0 = blockIdx.x * 64;

    float acc[4][4];
#pragma unroll
    for (int i = 0; i < 4; i++)
#pragma unroll
        for (int j = 0; j < 4; j++) acc[i][j] = 0.f;

    for (int k0 = 0; k0 < FIN; k0 += 32) {
        // load x tile 64 rows x 32 k (transposed into SMEM)
#pragma unroll
        for (int l = 0; l < 2; l++) {
            int idx = tid * 2 + l;          // float4 index 0..511
            int r   = idx >> 3;             // 8 float4 per row
            int kq  = (idx & 7) << 2;
            float4 v = *(const float4*)(x + (size_t)(row0 + r) * FIN + k0 + kq);
            xT[kq + 0][r] = v.x; xT[kq + 1][r] = v.y;
            xT[kq + 2][r] = v.z; xT[kq + 3][r] = v.w;
        }
        // load W tile 32 k x 64 c
#pragma unroll
        for (int l = 0; l < 2; l++) {
            int idx = tid * 2 + l;
            int kk  = idx >> 4;             // 16 float4 per k-row
            int cq  = (idx & 15) << 2;
            *(float4*)&Ws[kk][cq] = *(const float4*)(W + (size_t)(k0 + kk) * FOUT + cq);
        }
        __syncthreads();
#pragma unroll
        for (int kk = 0; kk < 32; kk++) {
            float4 xa = *(const float4*)&xT[kk][ty * 4];
            float4 wb = *(const float4*)&Ws[kk][tx * 4];
            float av[4] = {xa.x, xa.y, xa.z, xa.w};
            float bv[4] = {wb.x, wb.y, wb.z, wb.w};
#pragma unroll
            for (int i = 0; i < 4; i++)
#pragma unroll
                for (int j = 0; j < 4; j++)
                    acc[i][j] = fmaf(av[i], bv[j], acc[i][j]);
        }
        __syncthreads();
    }
#pragma unroll
    for (int i = 0; i < 4; i++) {
        float4 v = make_float4(acc[i][0], acc[i][1], acc[i][2], acc[i][3]);
        *(float4*)(g_h + (size_t)(row0 + ty * 4 + i) * FOUT + tx * 4) = v;
    }
}

// ---------------------------------------------------------------------------
// K2: a1[i] = h[i,:] @ a[0:64],  a2[i] = h[i,:] @ a[64:128]. One warp per row.
// ---------------------------------------------------------------------------
__global__ __launch_bounds__(256) void k2_att(const float* __restrict__ a) {
    const int warp = (blockIdx.x * blockDim.x + threadIdx.x) >> 5;
    const int lane = threadIdx.x & 31;
    if (warp >= NROWS) return;
    const float* hrow = g_h + (size_t)warp * FOUT;
    float v0 = hrow[lane], v1 = hrow[lane + 32];
    float s1 = v0 * a[lane]      + v1 * a[lane + 32];
    float s2 = v0 * a[64 + lane] + v1 * a[96 + lane];
#pragma unroll
    for (int o = 16; o; o >>= 1) {
        s1 += __shfl_xor_sync(0xffffffffu, s1, o);
        s2 += __shfl_xor_sync(0xffffffffu, s2, o);
    }
    if (lane == 0) { g_a1[warp] = s1; g_a2[warp] = s2; }
}

// K2b: global max of a2 (single block, deterministic)
__global__ __launch_bounds__(256) void k2b_max() {
    __shared__ float sm[256];
    float m = -1e30f;
    for (int i = threadIdx.x; i < NROWS; i += 256) m = fmaxf(m, g_a2[i]);
    sm[threadIdx.x] = m;
    __syncthreads();
    for (int s = 128; s; s >>= 1) {
        if (threadIdx.x < s) sm[threadIdx.x] = fmaxf(sm[threadIdx.x], sm[threadIdx.x + s]);
        __syncthreads();
    }
    if (threadIdx.x == 0) g_a2max = sm[0];
}

// ---------------------------------------------------------------------------
// K3: fused masked-softmax + att@h + elu.
// One CTA = 64 output rows. Stream adj in 64x64 tiles, prefetched in registers.
// P tile stored transposed in SMEM; 4x4 register-tiled FP32 accumulate.
// Softmax shift M_i = LR(a1_i + max_j a2_j) >= all scores -> no rescaling.
// ---------------------------------------------------------------------------
__global__ __launch_bounds__(256) void k3_fused(const float* __restrict__ adj,
                                                float* __restrict__ out) {
    __shared__ __align__(16) float Ps[64][68];   // [j][row]
    __shared__ __align__(16) float Hs[64][68];   // [j][col]
    __shared__ float denom_s[64];

    const int tid  = threadIdx.x;
    const int row0 = blockIdx.x * 64;

    // P-stage mapping: thread -> (row pr, 16 consecutive j starting at pj)
    const int pr = tid >> 2;
    const int pj = (tid & 3) << 4;
    const float a1r = g_a1[row0 + pr];
    const float sM  = a1r + g_a2max;
    const float Mr  = fmaxf(sM, ALPHA * sM);
    float dsum = 0.f;

    // GEMM mapping: thread (ty, tx) owns rows ty*4..+3, cols tx*4..+3
    const int ty = tid >> 4, tx = tid & 15;
    float acc[4][4];
#pragma unroll
    for (int i = 0; i < 4; i++)
#pragma unroll
        for (int c = 0; c < 4; c++) acc[i][c] = 0.f;

    // H-load mapping
    const int hj = tid >> 2;
    const int hc = (tid & 3) << 4;

    const float* arow = adj + (size_t)(row0 + pr) * NROWS + pj;

    // prefetch adj tile 0 into registers
    float4 aregs[4];
#pragma unroll
    for (int q = 0; q < 4; q++) aregs[q] = *(const float4*)(arow + q * 4);

    for (int j0 = 0; j0 < NROWS; j0 += 64) {
        // load h tile (L2-resident after first sweep)
        {
            const float* hp = g_h + (size_t)(j0 + hj) * FOUT + hc;
#pragma unroll
            for (int l = 0; l < 4; l++)
                *(float4*)&Hs[hj][hc + l * 4] = *(const float4*)(hp + l * 4);
        }
        // P stage: p = adj>0 ? exp(LR(a1_i + a2_j) - M_i) : 0
#pragma unroll
        for (int q = 0; q < 4; q++) {
            float4 av  = aregs[q];
            float4 a2v = *(const float4*)(g_a2 + j0 + pj + q * 4);
            float aa[4]  = {av.x, av.y, av.z, av.w};
            float a2a[4] = {a2v.x, a2v.y, a2v.z, a2v.w};
#pragma unroll
            for (int i = 0; i < 4; i++) {
                float s = a1r + a2a[i];
                float e = fmaxf(s, ALPHA * s);
                float p = (aa[i] > 0.f) ? __expf(e - Mr) : 0.f;
                dsum += p;
                Ps[pj + q * 4 + i][pr] = p;
            }
        }
        __syncthreads();

        // prefetch next adj tile while GEMM runs (hides DRAM latency)
        if (j0 + 64 < NROWS) {
            const float* an = arow + j0 + 64;
#pragma unroll
            for (int q = 0; q < 4; q++) aregs[q] = *(const float4*)(an + q * 4);
        }

        // GEMM stage: acc += P^T[r, j] * H[j, c]
#pragma unroll 16
        for (int j = 0; j < 64; j++) {
            float4 p4 = *(const float4*)&Ps[j][ty * 4];
            float4 h4 = *(const float4*)&Hs[j][tx * 4];
            float pa[4] = {p4.x, p4.y, p4.z, p4.w};
            float ha[4] = {h4.x, h4.y, h4.z, h4.w};
#pragma unroll
            for (int i = 0; i < 4; i++)
#pragma unroll
                for (int c = 0; c < 4; c++)
                    acc[i][c] = fmaf(pa[i], ha[c], acc[i][c]);
        }
        __syncthreads();
    }

    // reduce denominator across the 4 threads sharing a row (consecutive lanes)
    dsum += __shfl_xor_sync(0xffffffffu, dsum, 1);
    dsum += __shfl_xor_sync(0xffffffffu, dsum, 2);
    if ((tid & 3) == 0) denom_s[pr] = dsum;
    __syncthreads();

    // epilogue: normalize + elu, write out
#pragma unroll
    for (int i = 0; i < 4; i++) {
        float inv = 1.f / denom_s[ty * 4 + i];
        float4 v;
        float t0 = acc[i][0] * inv; v.x = t0 > 0.f ? t0 : expm1f(t0);
        float t1 = acc[i][1] * inv; v.y = t1 > 0.f ? t1 : expm1f(t1);
        float t2 = acc[i][2] * inv; v.z = t2 > 0.f ? t2 : expm1f(t2);
        float t3 = acc[i][3] * inv; v.w = t3 > 0.f ? t3 : expm1f(t3);
        *(float4*)(out + (size_t)(row0 + ty * 4 + i) * FOUT + tx * 4) = v;
    }
}

// ---------------------------------------------------------------------------
extern "C" void kernel_launch(void* const* d_in, const int* in_sizes, int n_in,
                              void* d_out, int out_size) {
    const float *x = nullptr, *adj = nullptr, *W = nullptr, *a = nullptr;
    for (int i = 0; i < n_in; i++) {
        switch (in_sizes[i]) {
            case NROWS * FIN:   x   = (const float*)d_in[i]; break;  // 4194304
            case NROWS * NROWS: adj = (const float*)d_in[i]; break;  // 67108864 (int overflow-safe: fits)
            case FIN * FOUT:    W   = (const float*)d_in[i]; break;  // 32768
            case 2 * FOUT:      a   = (const float*)d_in[i]; break;  // 128
        }
    }
    float* out = (float*)d_out;

    k1_gemm<<<NROWS / 64, 256>>>(x, W);
    k2_att<<<NROWS / 8, 256>>>(a);
    k2b_max<<<1, 256>>>();
    k3_fused<<<NROWS / 64, 256>>>(adj, out);
}

// round 4
// speedup vs baseline: 2.0424x; 2.0424x over previous
#include <cuda_runtime.h>
#include <math.h>

#define NROWS 8192
#define FIN   512
#define FOUT  64
#define ALPHA 0.2f
#define JSPLIT 2
#define JCHUNK (NROWS / JSPLIT)

// Scratch (no cudaMalloc allowed)
__device__ float g_h[NROWS * FOUT];   // h = x @ W
__device__ float g_a1[NROWS];
__device__ float g_a2[NROWS];
__device__ float g_a2max;
__device__ float g_e1p[NROWS], g_e1n[NROWS];   // per-row factors
__device__ float g_e2p[NROWS], g_e2n[NROWS];   // per-col factors
__device__ float g_pacc[JSPLIT][NROWS * FOUT]; // split-j partial accumulators
__device__ float g_pden[JSPLIT][NROWS];        // split-j partial denominators

__device__ __forceinline__ float cvt_tf32(float x) {
    unsigned r;
    asm("cvt.rna.tf32.f32 %0, %1;" : "=r"(r) : "f"(x));
    return __uint_as_float(r);
}

__device__ __forceinline__ void mma_tf32(float c[4],
                                         unsigned a0, unsigned a1, unsigned a2, unsigned a3,
                                         unsigned b0, unsigned b1) {
    asm volatile(
        "mma.sync.aligned.m16n8k8.row.col.f32.tf32.tf32.f32 "
        "{%0,%1,%2,%3}, {%4,%5,%6,%7}, {%8,%9}, {%0,%1,%2,%3};"
        : "+f"(c[0]), "+f"(c[1]), "+f"(c[2]), "+f"(c[3])
        : "r"(a0), "r"(a1), "r"(a2), "r"(a3), "r"(b0), "r"(b1));
}

// ---------------------------------------------------------------------------
// K1: h = x @ W   (8192x512 @ 512x64), FP32, 64x64 CTA tile, 4x4 per thread
// ---------------------------------------------------------------------------
__global__ __launch_bounds__(256) void k1_gemm(const float* __restrict__ x,
                                               const float* __restrict__ W) {
    __shared__ __align__(16) float xT[32][68];
    __shared__ __align__(16) float Ws[32][68];
    const int tid = threadIdx.x;
    const int ty = tid >> 4, tx = tid & 15;
    const int row0 = blockIdx.x * 64;

    float acc[4][4];
#pragma unroll
    for (int i = 0; i < 4; i++)
#pragma unroll
        for (int j = 0; j < 4; j++) acc[i][j] = 0.f;

    for (int k0 = 0; k0 < FIN; k0 += 32) {
#pragma unroll
        for (int l = 0; l < 2; l++) {
            int idx = tid * 2 + l;
            int r = idx >> 3;
            int kq = (idx & 7) << 2;
            float4 v = *(const float4*)(x + (size_t)(row0 + r) * FIN + k0 + kq);
            xT[kq + 0][r] = v.x; xT[kq + 1][r] = v.y;
            xT[kq + 2][r] = v.z; xT[kq + 3][r] = v.w;
        }
#pragma unroll
        for (int l = 0; l < 2; l++) {
            int idx = tid * 2 + l;
            int kk = idx >> 4;
            int cq = (idx & 15) << 2;
            *(float4*)&Ws[kk][cq] = *(const float4*)(W + (size_t)(k0 + kk) * FOUT + cq);
        }
        __syncthreads();
#pragma unroll
        for (int kk = 0; kk < 32; kk++) {
            float4 xa = *(const float4*)&xT[kk][ty * 4];
            float4 wb = *(const float4*)&Ws[kk][tx * 4];
            float av[4] = {xa.x, xa.y, xa.z, xa.w};
            float bv[4] = {wb.x, wb.y, wb.z, wb.w};
#pragma unroll
            for (int i = 0; i < 4; i++)
#pragma unroll
                for (int j = 0; j < 4; j++)
                    acc[i][j] = fmaf(av[i], bv[j], acc[i][j]);
        }
        __syncthreads();
    }
#pragma unroll
    for (int i = 0; i < 4; i++) {
        float4 v = make_float4(acc[i][0], acc[i][1], acc[i][2], acc[i][3]);
        *(float4*)(g_h + (size_t)(row0 + ty * 4 + i) * FOUT + tx * 4) = v;
    }
}

// ---------------------------------------------------------------------------
// K2: a1[i] = h[i,:] @ a[0:64],  a2[i] = h[i,:] @ a[64:128]. One warp per row.
// ---------------------------------------------------------------------------
__global__ __launch_bounds__(256) void k2_att(const float* __restrict__ a) {
    const int warp = (blockIdx.x * blockDim.x + threadIdx.x) >> 5;
    const int lane = threadIdx.x & 31;
    if (warp >= NROWS) return;
    const float* hrow = g_h + (size_t)warp * FOUT;
    float v0 = hrow[lane], v1 = hrow[lane + 32];
    float s1 = v0 * a[lane]      + v1 * a[lane + 32];
    float s2 = v0 * a[64 + lane] + v1 * a[96 + lane];
#pragma unroll
    for (int o = 16; o; o >>= 1) {
        s1 += __shfl_xor_sync(0xffffffffu, s1, o);
        s2 += __shfl_xor_sync(0xffffffffu, s2, o);
    }
    if (lane == 0) { g_a1[warp] = s1; g_a2[warp] = s2; }
}

// K2b: global max of a2 (single block, deterministic)
__global__ __launch_bounds__(256) void k2b_max() {
    __shared__ float sm[256];
    float m = -1e30f;
    for (int i = threadIdx.x; i < NROWS; i += 256) m = fmaxf(m, g_a2[i]);
    sm[threadIdx.x] = m;
    __syncthreads();
    for (int s = 128; s; s >>= 1) {
        if (threadIdx.x < s) sm[threadIdx.x] = fmaxf(sm[threadIdx.x], sm[threadIdx.x + s]);
        __syncthreads();
    }
    if (threadIdx.x == 0) g_a2max = sm[0];
}

// K2c: precompute exp factors. p_ij factorizes per LeakyReLU branch:
//   s>=0: exp(s-M)  = e1p_i * e2p_j,   s<0: exp(a*s-M) = e1n_i * e2n_j
// All four factors lie in (0,1].
__global__ __launch_bounds__(256) void k2c_pre() {
    int i = blockIdx.x * 256 + threadIdx.x;
    float a2m = g_a2max;
    float sM = g_a1[i] + a2m;
    float M = fmaxf(sM, ALPHA * sM);
    g_e1p[i] = expf(sM - M);
    g_e1n[i] = expf(ALPHA * sM - M);
    float d = g_a2[i] - a2m;
    g_e2p[i] = expf(d);
    g_e2n[i] = expf(ALPHA * d);
}

// ---------------------------------------------------------------------------
// K3: fused masked-softmax + att@h via tf32 mma.sync. No exp in inner loop.
// CTA: 64 rows x 4096 j (split-j over blockIdx.y). 8 warps: wy(0..3) x wx(0..1)
// -> each warp m16 x n32. Partial acc/denom to global scratch.
// ---------------------------------------------------------------------------
__global__ __launch_bounds__(256) void k3_fused(const float* __restrict__ adj) {
    __shared__ __align__(16) float Ps[64][68];  // [row][j]  pitch 68: A-frags conflict-free
    __shared__ __align__(16) float Hs[64][72];  // [j][col]  pitch 72: B-frags conflict-free
    __shared__ __align__(16) float s2[3][64];   // a2 / e2p / e2n for current j-tile

    const int tid = threadIdx.x;
    const int row0 = blockIdx.x * 64;
    const int split = blockIdx.y;
    const int jbase = split * JCHUNK;

    // P-build mapping: thread -> (row pr, 16 j's from pj)
    const int pr = tid >> 2;
    const int pj = (tid & 3) << 4;
    const float a1r = g_a1[row0 + pr];
    const float e1p = g_e1p[row0 + pr];
    const float e1n = g_e1n[row0 + pr];
    float dsum = 0.f;

    // mma mapping
    const int lane = tid & 31, warp = tid >> 5;
    const int wy = warp >> 1, wx = warp & 1;
    const int g = lane >> 2, t4 = lane & 3;
    float acc[4][4];
#pragma unroll
    for (int nf = 0; nf < 4; nf++)
#pragma unroll
        for (int c = 0; c < 4; c++) acc[nf][c] = 0.f;

    // H-load mapping
    const int hj = tid >> 2, hc = (tid & 3) << 4;

    // s2 staging source (threads 0..47)
    const float* s2src = nullptr;
    int s2which = 0, s2pos = 0;
    if (tid < 48) {
        s2which = tid >> 4;
        s2pos = (tid & 15) << 2;
        s2src = (s2which == 0 ? g_a2 : (s2which == 1 ? g_e2p : g_e2n)) + jbase + s2pos;
    }

    const float* arow = adj + (size_t)(row0 + pr) * NROWS + jbase + pj;

    // prefetch adj tile 0 + s2 tile 0
    float4 aregs[4];
#pragma unroll
    for (int q = 0; q < 4; q++) aregs[q] = *(const float4*)(arow + q * 4);
    if (tid < 48) *(float4*)&s2[s2which][s2pos] = *(const float4*)s2src;
    __syncthreads();

    for (int jt = 0; jt < JCHUNK; jt += 64) {
        // --- stage A: load H tile (cvt to tf32), build P tile ---
        {
            const float* hp = g_h + (size_t)(jbase + jt + hj) * FOUT + hc;
#pragma unroll
            for (int l = 0; l < 4; l++) {
                float4 v = *(const float4*)(hp + l * 4);
                v.x = cvt_tf32(v.x); v.y = cvt_tf32(v.y);
                v.z = cvt_tf32(v.z); v.w = cvt_tf32(v.w);
                *(float4*)&Hs[hj][hc + l * 4] = v;
            }
        }
#pragma unroll
        for (int q = 0; q < 4; q++) {
            float4 av  = aregs[q];
            float4 a2v = *(const float4*)&s2[0][pj + q * 4];
            float4 epv = *(const float4*)&s2[1][pj + q * 4];
            float4 env = *(const float4*)&s2[2][pj + q * 4];
            float aa[4] = {av.x, av.y, av.z, av.w};
            float a2a[4] = {a2v.x, a2v.y, a2v.z, a2v.w};
            float epa[4] = {epv.x, epv.y, epv.z, epv.w};
            float ena[4] = {env.x, env.y, env.z, env.w};
            float pp[4];
#pragma unroll
            for (int l = 0; l < 4; l++) {
                float s = a1r + a2a[l];
                float f1 = (s >= 0.f) ? e1p : e1n;
                float f2 = (s >= 0.f) ? epa[l] : ena[l];
                float p = aa[l] * f1 * f2;   // adj is exactly 0.0/1.0
                p = cvt_tf32(p);
                dsum += p;
                pp[l] = p;
            }
            *(float4*)&Ps[pr][pj + q * 4] = make_float4(pp[0], pp[1], pp[2], pp[3]);
        }
        __syncthreads();

        // --- prefetch next adj + s2 tile (hides DRAM latency under mma) ---
        if (jt + 64 < JCHUNK) {
            const float* an = arow + jt + 64;
#pragma unroll
            for (int q = 0; q < 4; q++) aregs[q] = *(const float4*)(an + q * 4);
            if (tid < 48) *(float4*)&s2[s2which][s2pos] = *(const float4*)(s2src + jt + 64);
        }

        // --- stage B: tf32 mma over Ps (A, m16k8) x Hs (B, k8n8) ---
#pragma unroll
        for (int kk = 0; kk < 8; kk++) {
            const int jk = kk * 8;
            unsigned a0 = __float_as_uint(Ps[wy * 16 + g][jk + t4]);
            unsigned a1 = __float_as_uint(Ps[wy * 16 + g + 8][jk + t4]);
            unsigned a2 = __float_as_uint(Ps[wy * 16 + g][jk + t4 + 4]);
            unsigned a3 = __float_as_uint(Ps[wy * 16 + g + 8][jk + t4 + 4]);
#pragma unroll
            for (int nf = 0; nf < 4; nf++) {
                const int cw = wx * 32 + nf * 8;
                unsigned b0 = __float_as_uint(Hs[jk + t4][cw + g]);
                unsigned b1 = __float_as_uint(Hs[jk + t4 + 4][cw + g]);
                mma_tf32(acc[nf], a0, a1, a2, a3, b0, b1);
            }
        }
        __syncthreads();
    }

    // partial denominator: reduce across 4 threads sharing a row
    dsum += __shfl_xor_sync(0xffffffffu, dsum, 1);
    dsum += __shfl_xor_sync(0xffffffffu, dsum, 2);
    if ((tid & 3) == 0) g_pden[split][row0 + pr] = dsum;

    // partial accumulator: c0,c1 = (row g, col 2t,2t+1); c2,c3 = row g+8
    float* pa = g_pacc[split];
#pragma unroll
    for (int nf = 0; nf < 4; nf++) {
        const int col = wx * 32 + nf * 8 + t4 * 2;
        const int r = row0 + wy * 16 + g;
        *(float2*)&pa[(size_t)r * FOUT + col]       = make_float2(acc[nf][0], acc[nf][1]);
        *(float2*)&pa[(size_t)(r + 8) * FOUT + col] = make_float2(acc[nf][2], acc[nf][3]);
    }
}

// ---------------------------------------------------------------------------
// K4: epilogue — merge split-j partials, normalize, ELU, write out.
// ---------------------------------------------------------------------------
__global__ __launch_bounds__(256) void k4_epi(float* __restrict__ out) {
    const int idx = blockIdx.x * 256 + threadIdx.x;   // 131072 threads
    const int row = idx >> 4;
    const int cg = (idx & 15) << 2;
    float4 v0 = *(const float4*)&g_pacc[0][(size_t)row * FOUT + cg];
    float4 v1 = *(const float4*)&g_pacc[1][(size_t)row * FOUT + cg];
    float inv = 1.f / (g_pden[0][row] + g_pden[1][row]);
    float4 r;
    float t0 = (v0.x + v1.x) * inv; r.x = t0 > 0.f ? t0 : expm1f(t0);
    float t1 = (v0.y + v1.y) * inv; r.y = t1 > 0.f ? t1 : expm1f(t1);
    float t2 = (v0.z + v1.z) * inv; r.z = t2 > 0.f ? t2 : expm1f(t2);
    float t3 = (v0.w + v1.w) * inv; r.w = t3 > 0.f ? t3 : expm1f(t3);
    *(float4*)&out[(size_t)row * FOUT + cg] = r;
}

// ---------------------------------------------------------------------------
extern "C" void kernel_launch(void* const* d_in, const int* in_sizes, int n_in,
                              void* d_out, int out_size) {
    const float *x = nullptr, *adj = nullptr, *W = nullptr, *a = nullptr;
    for (int i = 0; i < n_in; i++) {
        switch (in_sizes[i]) {
            case NROWS * FIN:   x   = (const float*)d_in[i]; break;
            case NROWS * NROWS: adj = (const float*)d_in[i]; break;
            case FIN * FOUT:    W   = (const float*)d_in[i]; break;
            case 2 * FOUT:      a   = (const float*)d_in[i]; break;
        }
    }
    float* out = (float*)d_out;

    k1_gemm<<<NROWS / 64, 256>>>(x, W);
    k2_att<<<NROWS / 8, 256>>>(a);
    k2b_max<<<1, 256>>>();
    k2c_pre<<<NROWS / 256, 256>>>();
    dim3 g3(NROWS / 64, JSPLIT);
    k3_fused<<<g3, 256>>>(adj);
    k4_epi<<<NROWS * FOUT / 4 / 256, 256>>>(out);
}

// round 6
// speedup vs baseline: 2.9291x; 1.4342x over previous
#include <cuda_runtime.h>
#include <cuda_fp16.h>
#include <math.h>

#define NROWS 8192
#define FIN   512
#define FOUT  64
#define ALPHA 0.2f
#define JSPLIT 4
#define JCHUNK (NROWS / JSPLIT)

// Scratch (no cudaMalloc allowed)
__device__ __align__(16) float  g_h[NROWS * FOUT];    // h = x @ W (fp32)
__device__ __align__(16) __half g_hT[FOUT * NROWS];   // h transposed, fp16: [col][row]
__device__ float  g_a1[NROWS];
__device__ float  g_a2[NROWS];
__device__ float  g_e1p[NROWS], g_e1n[NROWS];   // per-row factors
__device__ float  g_e2p[NROWS], g_e2n[NROWS];   // per-col factors
__device__ __align__(16) float g_pacc[JSPLIT][NROWS * FOUT]; // split-j partial acc
__device__ float  g_pden[JSPLIT][NROWS];        // split-j partial denominators

__device__ __forceinline__ void mma_f16(float c[4],
                                        unsigned a0, unsigned a1, unsigned a2, unsigned a3,
                                        unsigned b0, unsigned b1) {
    asm volatile(
        "mma.sync.aligned.m16n8k16.row.col.f32.f16.f16.f32 "
        "{%0,%1,%2,%3}, {%4,%5,%6,%7}, {%8,%9}, {%0,%1,%2,%3};"
        : "+f"(c[0]), "+f"(c[1]), "+f"(c[2]), "+f"(c[3])
        : "r"(a0), "r"(a1), "r"(a2), "r"(a3), "r"(b0), "r"(b1));
}

// ---------------------------------------------------------------------------
// K1: h = x @ W   (8192x512 @ 512x64), FP32, 64x64 CTA tile, 4x4 per thread
// ---------------------------------------------------------------------------
__global__ __launch_bounds__(256) void k1_gemm(const float* __restrict__ x,
                                               const float* __restrict__ W) {
    __shared__ __align__(16) float xT[32][68];
    __shared__ __align__(16) float Ws[32][68];
    const int tid = threadIdx.x;
    const int ty = tid >> 4, tx = tid & 15;
    const int row0 = blockIdx.x * 64;

    float acc[4][4];
#pragma unroll
    for (int i = 0; i < 4; i++)
#pragma unroll
        for (int j = 0; j < 4; j++) acc[i][j] = 0.f;

    for (int k0 = 0; k0 < FIN; k0 += 32) {
#pragma unroll
        for (int l = 0; l < 2; l++) {
            int idx = tid * 2 + l;
            int r = idx >> 3;
            int kq = (idx & 7) << 2;
            float4 v = *(const float4*)(x + (size_t)(row0 + r) * FIN + k0 + kq);
            xT[kq + 0][r] = v.x; xT[kq + 1][r] = v.y;
            xT[kq + 2][r] = v.z; xT[kq + 3][r] = v.w;
        }
#pragma unroll
        for (int l = 0; l < 2; l++) {
            int idx = tid * 2 + l;
            int kk = idx >> 4;
            int cq = (idx & 15) << 2;
            *(float4*)&Ws[kk][cq] = *(const float4*)(W + (size_t)(k0 + kk) * FOUT + cq);
        }
        __syncthreads();
#pragma unroll
        for (int kk = 0; kk < 32; kk++) {
            float4 xa = *(const float4*)&xT[kk][ty * 4];
            float4 wb = *(const float4*)&Ws[kk][tx * 4];
            float av[4] = {xa.x, xa.y, xa.z, xa.w};
            float bv[4] = {wb.x, wb.y, wb.z, wb.w};
#pragma unroll
            for (int i = 0; i < 4; i++)
#pragma unroll
                for (int j = 0; j < 4; j++)
                    acc[i][j] = fmaf(av[i], bv[j], acc[i][j]);
        }
        __syncthreads();
    }
#pragma unroll
    for (int i = 0; i < 4; i++) {
        float4 v = make_float4(acc[i][0], acc[i][1], acc[i][2], acc[i][3]);
        *(float4*)(g_h + (size_t)(row0 + ty * 4 + i) * FOUT + tx * 4) = v;
    }
}

// ---------------------------------------------------------------------------
// K1t: build g_hT[col][row] = (half)g_h[row][col]. SMEM-tiled transpose.
// NOTE: ht pitch 65 -> conflict-free column reads; all SMEM stores are SCALAR
// (pitch 65*4=260B is not float4-aligned for odd rows).
// ---------------------------------------------------------------------------
__global__ __launch_bounds__(256) void k1t_trans() {
    __shared__ float ht[64][65];
    const int tid = threadIdx.x;
    const int row0 = blockIdx.x * 64;
    {
        const int r = tid >> 2, cp = (tid & 3) * 16;
#pragma unroll
        for (int l = 0; l < 4; l++) {
            float4 v = *(const float4*)(g_h + (size_t)(row0 + r) * FOUT + cp + l * 4);
            ht[r][cp + l * 4 + 0] = v.x;
            ht[r][cp + l * 4 + 1] = v.y;
            ht[r][cp + l * 4 + 2] = v.z;
            ht[r][cp + l * 4 + 3] = v.w;
        }
    }
    __syncthreads();
    {
        const int c = tid >> 2, rp = (tid & 3) * 16;
        unsigned u[8];
#pragma unroll
        for (int i = 0; i < 8; i++) {
            __half2 h2 = __floats2half2_rn(ht[rp + i * 2][c], ht[rp + i * 2 + 1][c]);
            u[i] = *(unsigned*)&h2;
        }
        __half* dst = g_hT + (size_t)c * NROWS + row0 + rp;
        ((uint4*)dst)[0] = make_uint4(u[0], u[1], u[2], u[3]);
        ((uint4*)dst)[1] = make_uint4(u[4], u[5], u[6], u[7]);
    }
}

// ---------------------------------------------------------------------------
// K2: a1[i] = h[i,:] @ a[0:64],  a2[i] = h[i,:] @ a[64:128]. One warp per row.
// ---------------------------------------------------------------------------
__global__ __launch_bounds__(256) void k2_att(const float* __restrict__ a) {
    const int warp = (blockIdx.x * blockDim.x + threadIdx.x) >> 5;
    const int lane = threadIdx.x & 31;
    if (warp >= NROWS) return;
    const float* hrow = g_h + (size_t)warp * FOUT;
    float v0 = hrow[lane], v1 = hrow[lane + 32];
    float s1 = v0 * a[lane]      + v1 * a[lane + 32];
    float s2 = v0 * a[64 + lane] + v1 * a[96 + lane];
#pragma unroll
    for (int o = 16; o; o >>= 1) {
        s1 += __shfl_xor_sync(0xffffffffu, s1, o);
        s2 += __shfl_xor_sync(0xffffffffu, s2, o);
    }
    if (lane == 0) { g_a1[warp] = s1; g_a2[warp] = s2; }
}

// ---------------------------------------------------------------------------
// K2bc: fused max(a2) + exp-factor precompute.
//   s>=0: exp(s-M)  = e1p_i * e2p_j,   s<0: exp(a*s-M) = e1n_i * e2n_j
// ---------------------------------------------------------------------------
__global__ __launch_bounds__(256) void k2bc_pre() {
    __shared__ float sm[256];
    float m = -1e30f;
    for (int i = threadIdx.x; i < NROWS; i += 256) m = fmaxf(m, g_a2[i]);
    sm[threadIdx.x] = m;
    __syncthreads();
    for (int s = 128; s; s >>= 1) {
        if (threadIdx.x < s) sm[threadIdx.x] = fmaxf(sm[threadIdx.x], sm[threadIdx.x + s]);
        __syncthreads();
    }
    const float a2m = sm[0];
    const int i = blockIdx.x * 256 + threadIdx.x;
    float sM = g_a1[i] + a2m;
    float M = fmaxf(sM, ALPHA * sM);
    g_e1p[i] = expf(sM - M);
    g_e1n[i] = expf(ALPHA * sM - M);
    float d = g_a2[i] - a2m;
    g_e2p[i] = expf(d);
    g_e2n[i] = expf(ALPHA * d);
}

// ---------------------------------------------------------------------------
// K3: fused masked-softmax + att@h via fp16 mma.m16n8k16. No exp inner loop.
// CTA: 64 rows x 2048 j (split-j over blockIdx.y). 8 warps: wy(0..3) x wx(0..1)
// -> each warp m16 x n32. P fp16 SMEM [row][j]; H fp16 SMEM [col][j]
// (pre-transposed global) so every fragment reg is one conflict-free LDS.32.
// ---------------------------------------------------------------------------
__global__ __launch_bounds__(256) void k3_fused(const float* __restrict__ adj) {
    __shared__ __align__(16) __half Ps[64][72];  // pitch 72h = 144B (16-mult)
    __shared__ __align__(16) __half Hs[64][72];
    __shared__ __align__(16) float s2[3][64];    // a2 / e2p / e2n for j-tile

    const int tid = threadIdx.x;
    const int row0 = blockIdx.x * 64;
    const int split = blockIdx.y;
    const int jbase = split * JCHUNK;

    // P-build mapping: thread -> (row pr, 16 j's from pj)
    const int pr = tid >> 2;
    const int pj = (tid & 3) << 4;
    const float a1r = g_a1[row0 + pr];
    const float e1p = g_e1p[row0 + pr];
    const float e1n = g_e1n[row0 + pr];
    float dsum = 0.f;

    // mma mapping
    const int lane = tid & 31, warp = tid >> 5;
    const int wy = warp >> 1, wx = warp & 1;
    const int g = lane >> 2, t4 = lane & 3;
    float acc[4][4];
#pragma unroll
    for (int nf = 0; nf < 4; nf++)
#pragma unroll
        for (int c = 0; c < 4; c++) acc[nf][c] = 0.f;

    // H-load mapping: 4 threads per col, each 16 halves (32B)
    const int hcol = tid >> 2, hpart = tid & 3;
    const __half* hsrc = g_hT + (size_t)hcol * NROWS + jbase + hpart * 16;

    // s2 staging (threads 0..47)
    const float* s2src = nullptr;
    int s2which = 0, s2pos = 0;
    if (tid < 48) {
        s2which = tid >> 4;
        s2pos = (tid & 15) << 2;
        s2src = (s2which == 0 ? g_a2 : (s2which == 1 ? g_e2p : g_e2n)) + jbase + s2pos;
    }

    const float* arow = adj + (size_t)(row0 + pr) * NROWS + jbase + pj;

    // prefetch adj tile 0 + s2 tile 0
    float4 aregs[4];
#pragma unroll
    for (int q = 0; q < 4; q++) aregs[q] = *(const float4*)(arow + q * 4);
    if (tid < 48) *(float4*)&s2[s2which][s2pos] = *(const float4*)s2src;
    __syncthreads();

    for (int jt = 0; jt < JCHUNK; jt += 64) {
        // --- stage A: load H tile (fp16, pre-transposed), build P tile (fp16) ---
        {
            const uint4* src = (const uint4*)(hsrc + jt);
            *(uint4*)&Hs[hcol][hpart * 16]     = src[0];
            *(uint4*)&Hs[hcol][hpart * 16 + 8] = src[1];
        }
        unsigned pph[8];
#pragma unroll
        for (int q = 0; q < 4; q++) {
            float4 av  = aregs[q];
            float4 a2v = *(const float4*)&s2[0][pj + q * 4];
            float4 epv = *(const float4*)&s2[1][pj + q * 4];
            float4 env = *(const float4*)&s2[2][pj + q * 4];
            float aa[4]  = {av.x, av.y, av.z, av.w};
            float a2a[4] = {a2v.x, a2v.y, a2v.z, a2v.w};
            float epa[4] = {epv.x, epv.y, epv.z, epv.w};
            float ena[4] = {env.x, env.y, env.z, env.w};
            float pf[4];
#pragma unroll
            for (int l = 0; l < 4; l++) {
                float s = a1r + a2a[l];
                float f1 = (s >= 0.f) ? e1p : e1n;
                float f2 = (s >= 0.f) ? epa[l] : ena[l];
                float p = aa[l] * f1 * f2;   // adj is exactly 0.0/1.0
                dsum += p;
                pf[l] = p;
            }
            __half2 h0 = __floats2half2_rn(pf[0], pf[1]);
            __half2 h1 = __floats2half2_rn(pf[2], pf[3]);
            pph[q * 2]     = *(unsigned*)&h0;
            pph[q * 2 + 1] = *(unsigned*)&h1;
        }
        *(uint4*)&Ps[pr][pj]     = make_uint4(pph[0], pph[1], pph[2], pph[3]);
        *(uint4*)&Ps[pr][pj + 8] = make_uint4(pph[4], pph[5], pph[6], pph[7]);
        __syncthreads();

        // --- prefetch next adj + s2 tile (hides DRAM latency under mma) ---
        if (jt + 64 < JCHUNK) {
            const float* an = arow + jt + 64;
#pragma unroll
            for (int q = 0; q < 4; q++) aregs[q] = *(const float4*)(an + q * 4);
            if (tid < 48) *(float4*)&s2[s2which][s2pos] = *(const float4*)(s2src + jt + 64);
        }

        // --- stage B: fp16 mma m16n8k16 over Ps (A) x Hs (B) ---
#pragma unroll
        for (int kk = 0; kk < 4; kk++) {
            const int k0 = kk * 16;
            unsigned a0 = *(const unsigned*)&Ps[wy * 16 + g][k0 + 2 * t4];
            unsigned a1 = *(const unsigned*)&Ps[wy * 16 + g + 8][k0 + 2 * t4];
            unsigned a2 = *(const unsigned*)&Ps[wy * 16 + g][k0 + 2 * t4 + 8];
            unsigned a3 = *(const unsigned*)&Ps[wy * 16 + g + 8][k0 + 2 * t4 + 8];
#pragma unroll
            for (int nf = 0; nf < 4; nf++) {
                const int n0 = wx * 32 + nf * 8;
                unsigned b0 = *(const unsigned*)&Hs[n0 + g][k0 + 2 * t4];
                unsigned b1 = *(const unsigned*)&Hs[n0 + g][k0 + 2 * t4 + 8];
                mma_f16(acc[nf], a0, a1, a2, a3, b0, b1);
            }
        }
        __syncthreads();
    }

    // partial denominator: reduce across 4 threads sharing a row
    dsum += __shfl_xor_sync(0xffffffffu, dsum, 1);
    dsum += __shfl_xor_sync(0xffffffffu, dsum, 2);
    if ((tid & 3) == 0) g_pden[split][row0 + pr] = dsum;

    // partial accumulator: c0,c1 = (row g, col 2t4,2t4+1); c2,c3 = row g+8
    float* pa = g_pacc[split];
#pragma unroll
    for (int nf = 0; nf < 4; nf++) {
        const int col = wx * 32 + nf * 8 + t4 * 2;
        const int r = row0 + wy * 16 + g;
        *(float2*)&pa[(size_t)r * FOUT + col]       = make_float2(acc[nf][0], acc[nf][1]);
        *(float2*)&pa[(size_t)(r + 8) * FOUT + col] = make_float2(acc[nf][2], acc[nf][3]);
    }
}

// ---------------------------------------------------------------------------
// K4: epilogue — merge split-j partials, normalize, ELU, write out.
// ---------------------------------------------------------------------------
__global__ __launch_bounds__(256) void k4_epi(float* __restrict__ out) {
    const int idx = blockIdx.x * 256 + threadIdx.x;
    const int row = idx >> 4;
    const int cg = (idx & 15) << 2;
    float4 v = make_float4(0.f, 0.f, 0.f, 0.f);
    float den = 0.f;
#pragma unroll
    for (int s = 0; s < JSPLIT; s++) {
        float4 p = *(const float4*)&g_pacc[s][(size_t)row * FOUT + cg];
        v.x += p.x; v.y += p.y; v.z += p.z; v.w += p.w;
        den += g_pden[s][row];
    }
    float inv = 1.f / den;
    float4 r;
    float t0 = v.x * inv; r.x = t0 > 0.f ? t0 : expm1f(t0);
    float t1 = v.y * inv; r.y = t1 > 0.f ? t1 : expm1f(t1);
    float t2 = v.z * inv; r.z = t2 > 0.f ? t2 : expm1f(t2);
    float t3 = v.w * inv; r.w = t3 > 0.f ? t3 : expm1f(t3);
    *(float4*)&out[(size_t)row * FOUT + cg] = r;
}

// ---------------------------------------------------------------------------
extern "C" void kernel_launch(void* const* d_in, const int* in_sizes, int n_in,
                              void* d_out, int out_size) {
    const float *x = nullptr, *adj = nullptr, *W = nullptr, *a = nullptr;
    for (int i = 0; i < n_in; i++) {
        switch (in_sizes[i]) {
            case NROWS * FIN:   x   = (const float*)d_in[i]; break;
            case NROWS * NROWS: adj = (const float*)d_in[i]; break;
            case FIN * FOUT:    W   = (const float*)d_in[i]; break;
            case 2 * FOUT:      a   = (const float*)d_in[i]; break;
        }
    }
    float* out = (float*)d_out;

    k1_gemm<<<NROWS / 64, 256>>>(x, W);
    k1t_trans<<<NROWS / 64, 256>>>();
    k2_att<<<NROWS / 8, 256>>>(a);
    k2bc_pre<<<NROWS / 256, 256>>>();
    dim3 g3(NROWS / 64, JSPLIT);
    k3_fused<<<g3, 256>>>(adj);
    k4_epi<<<NROWS * FOUT / 4 / 256, 256>>>(out);
}

// round 8
// speedup vs baseline: 3.6213x; 1.2363x over previous
#include <cuda_runtime.h>
#include <cuda_fp16.h>
#include <math.h>

#define NROWS 8192
#define FIN   512
#define FOUT  64
#define ALPHA 0.2f
#define JSPLIT 4
#define JCHUNK (NROWS / JSPLIT)

// Scratch (no cudaMalloc allowed)
__device__ __align__(16) float  g_h[NROWS * FOUT];    // h = x @ W (fp32)
__device__ __align__(16) __half g_hT[FOUT * NROWS];   // h transposed, fp16: [col][row]
__device__ float  g_a1[NROWS];
__device__ float  g_a2[NROWS];
__device__ float  g_e1p[NROWS], g_e1n[NROWS];           // per-row factors (fp32)
__device__ __align__(16) __half g_a2h[NROWS];           // fp16 copies for k3
__device__ __align__(16) __half g_e2ph[NROWS];
__device__ __align__(16) __half g_e2nh[NROWS];
__device__ __align__(16) float g_pacc[JSPLIT][NROWS * FOUT];
__device__ float  g_pden[JSPLIT][NROWS];

__device__ __forceinline__ unsigned h2u(__half2 h) { return *(unsigned*)&h; }
__device__ __forceinline__ __half2 u2h(unsigned u) { return *(__half2*)&u; }

__device__ __forceinline__ void mma_f16(float c[4],
                                        unsigned a0, unsigned a1, unsigned a2, unsigned a3,
                                        unsigned b0, unsigned b1) {
    asm volatile(
        "mma.sync.aligned.m16n8k16.row.col.f32.f16.f16.f32 "
        "{%0,%1,%2,%3}, {%4,%5,%6,%7}, {%8,%9}, {%0,%1,%2,%3};"
        : "+f"(c[0]), "+f"(c[1]), "+f"(c[2]), "+f"(c[3])
        : "r"(a0), "r"(a1), "r"(a2), "r"(a3), "r"(b0), "r"(b1));
}

// ---------------------------------------------------------------------------
// K1: h = x @ W   (8192x512 @ 512x64), FP32, 64x64 CTA tile, 4x4 per thread
// ---------------------------------------------------------------------------
__global__ __launch_bounds__(256) void k1_gemm(const float* __restrict__ x,
                                               const float* __restrict__ W) {
    __shared__ __align__(16) float xT[32][68];
    __shared__ __align__(16) float Ws[32][68];
    const int tid = threadIdx.x;
    const int ty = tid >> 4, tx = tid & 15;
    const int row0 = blockIdx.x * 64;

    float acc[4][4];
#pragma unroll
    for (int i = 0; i < 4; i++)
#pragma unroll
        for (int j = 0; j < 4; j++) acc[i][j] = 0.f;

    for (int k0 = 0; k0 < FIN; k0 += 32) {
#pragma unroll
        for (int l = 0; l < 2; l++) {
            int idx = tid * 2 + l;
            int r = idx >> 3;
            int kq = (idx & 7) << 2;
            float4 v = *(const float4*)(x + (size_t)(row0 + r) * FIN + k0 + kq);
            xT[kq + 0][r] = v.x; xT[kq + 1][r] = v.y;
            xT[kq + 2][r] = v.z; xT[kq + 3][r] = v.w;
        }
#pragma unroll
        for (int l = 0; l < 2; l++) {
            int idx = tid * 2 + l;
            int kk = idx >> 4;
            int cq = (idx & 15) << 2;
            *(float4*)&Ws[kk][cq] = *(const float4*)(W + (size_t)(k0 + kk) * FOUT + cq);
        }
        __syncthreads();
#pragma unroll
        for (int kk = 0; kk < 32; kk++) {
            float4 xa = *(const float4*)&xT[kk][ty * 4];
            float4 wb = *(const float4*)&Ws[kk][tx * 4];
            float av[4] = {xa.x, xa.y, xa.z, xa.w};
            float bv[4] = {wb.x, wb.y, wb.z, wb.w};
#pragma unroll
            for (int i = 0; i < 4; i++)
#pragma unroll
                for (int j = 0; j < 4; j++)
                    acc[i][j] = fmaf(av[i], bv[j], acc[i][j]);
        }
        __syncthreads();
    }
#pragma unroll
    for (int i = 0; i < 4; i++) {
        float4 v = make_float4(acc[i][0], acc[i][1], acc[i][2], acc[i][3]);
        *(float4*)(g_h + (size_t)(row0 + ty * 4 + i) * FOUT + tx * 4) = v;
    }
}

// ---------------------------------------------------------------------------
// K1t: build g_hT[col][row] = (half)g_h[row][col]. SMEM-tiled transpose.
// ht pitch 65 -> conflict-free column reads; SMEM stores are SCALAR.
// ---------------------------------------------------------------------------
__global__ __launch_bounds__(256) void k1t_trans() {
    __shared__ float ht[64][65];
    const int tid = threadIdx.x;
    const int row0 = blockIdx.x * 64;
    {
        const int r = tid >> 2, cp = (tid & 3) * 16;
#pragma unroll
        for (int l = 0; l < 4; l++) {
            float4 v = *(const float4*)(g_h + (size_t)(row0 + r) * FOUT + cp + l * 4);
            ht[r][cp + l * 4 + 0] = v.x;
            ht[r][cp + l * 4 + 1] = v.y;
            ht[r][cp + l * 4 + 2] = v.z;
            ht[r][cp + l * 4 + 3] = v.w;
        }
    }
    __syncthreads();
    {
        const int c = tid >> 2, rp = (tid & 3) * 16;
        unsigned u[8];
#pragma unroll
        for (int i = 0; i < 8; i++) {
            __half2 h2 = __floats2half2_rn(ht[rp + i * 2][c], ht[rp + i * 2 + 1][c]);
            u[i] = *(unsigned*)&h2;
        }
        __half* dst = g_hT + (size_t)c * NROWS + row0 + rp;
        ((uint4*)dst)[0] = make_uint4(u[0], u[1], u[2], u[3]);
        ((uint4*)dst)[1] = make_uint4(u[4], u[5], u[6], u[7]);
    }
}

// ---------------------------------------------------------------------------
// K2: a1/a2 row projections. One warp per row.
// ---------------------------------------------------------------------------
__global__ __launch_bounds__(256) void k2_att(const float* __restrict__ a) {
    const int warp = (blockIdx.x * blockDim.x + threadIdx.x) >> 5;
    const int lane = threadIdx.x & 31;
    if (warp >= NROWS) return;
    const float* hrow = g_h + (size_t)warp * FOUT;
    float v0 = hrow[lane], v1 = hrow[lane + 32];
    float s1 = v0 * a[lane]      + v1 * a[lane + 32];
    float s2 = v0 * a[64 + lane] + v1 * a[96 + lane];
#pragma unroll
    for (int o = 16; o; o >>= 1) {
        s1 += __shfl_xor_sync(0xffffffffu, s1, o);
        s2 += __shfl_xor_sync(0xffffffffu, s2, o);
    }
    if (lane == 0) { g_a1[warp] = s1; g_a2[warp] = s2; }
}

// ---------------------------------------------------------------------------
// K2bc: fused max(a2) + exp-factor precompute (fp32 row factors, fp16 col
// factors). s>=0: exp(s-M)=e1p_i*e2p_j ; s<0: exp(a*s-M)=e1n_i*e2n_j.
// ---------------------------------------------------------------------------
__global__ __launch_bounds__(256) void k2bc_pre() {
    __shared__ float sm[256];
    float m = -1e30f;
    for (int i = threadIdx.x; i < NROWS; i += 256) m = fmaxf(m, g_a2[i]);
    sm[threadIdx.x] = m;
    __syncthreads();
    for (int s = 128; s; s >>= 1) {
        if (threadIdx.x < s) sm[threadIdx.x] = fmaxf(sm[threadIdx.x], sm[threadIdx.x + s]);
        __syncthreads();
    }
    const float a2m = sm[0];
    const int i = blockIdx.x * 256 + threadIdx.x;
    float a2i = g_a2[i];
    float sM = g_a1[i] + a2m;
    float M = fmaxf(sM, ALPHA * sM);
    g_e1p[i] = expf(sM - M);
    g_e1n[i] = expf(ALPHA * sM - M);
    float d = a2i - a2m;
    g_a2h[i]  = __float2half(a2i);
    g_e2ph[i] = __float2half(expf(d));
    g_e2nh[i] = __float2half(expf(ALPHA * d));
}

// ---------------------------------------------------------------------------
// K3: fused masked-softmax + att@h. fp16 mma m16n8k16. Half2 P-build,
// denominator via mma with B=ones, single-sync ping-pong pipeline.
// CTA: 64 rows x JCHUNK j. 8 warps: wy(0..3) x wx(0..1), warp = m16 x n32.
// ---------------------------------------------------------------------------
__global__ __launch_bounds__(256) void k3_fused(const float* __restrict__ adj) {
    __shared__ __align__(16) __half Ps[2][64][72];  // [buf][row][j]
    __shared__ __align__(16) __half Hs[2][64][72];  // [buf][col][j]
    __shared__ __align__(16) __half s2h[2][3][64];  // [buf][a2h/e2ph/e2nh][j]

    const int tid = threadIdx.x;
    const int row0 = blockIdx.x * 64;
    const int split = blockIdx.y;
    const int jbase = split * JCHUNK;

    // P-build mapping: thread -> (row pr, 16 j's from pj)
    const int pr = tid >> 2;
    const int pj = (tid & 3) << 4;
    const unsigned a1u  = h2u(__float2half2_rn(g_a1[row0 + pr]));
    const unsigned e1pu = h2u(__float2half2_rn(g_e1p[row0 + pr]));
    const unsigned e1nu = h2u(__float2half2_rn(g_e1n[row0 + pr]));
    const __half2 hzero = __float2half2_rn(0.f);

    // mma mapping
    const int lane = tid & 31, warp = tid >> 5;
    const int wy = warp >> 1, wx = warp & 1;
    const int g = lane >> 2, t4 = lane & 3;
    const unsigned ONEH2 = 0x3C003C00u;  // half2(1,1)
    float acc[4][4];
#pragma unroll
    for (int nf = 0; nf < 4; nf++)
#pragma unroll
        for (int c = 0; c < 4; c++) acc[nf][c] = 0.f;
    float accD[4] = {0.f, 0.f, 0.f, 0.f};  // denominator (wx==0 warps)

    // H-load mapping: 4 threads per col, 16 halves each
    const int hcol = tid >> 2, hpart = tid & 3;
    const __half* hsrc = g_hT + (size_t)hcol * NROWS + jbase + hpart * 16;

    // s2 staging (threads 0..23): which array, which 8-half chunk
    const int s2w = tid >> 3, s2part = tid & 7;
    const __half* s2src =
        (s2w == 0 ? g_a2h : (s2w == 1 ? g_e2ph : g_e2nh)) + jbase + s2part * 8;

    const float* arow = adj + (size_t)(row0 + pr) * NROWS + jbase + pj;

    // prologue: adj tile 0 regs + s2 tile 0 into buf 0
    float4 aregs[4];
#pragma unroll
    for (int q = 0; q < 4; q++) aregs[q] = *(const float4*)(arow + q * 4);
    if (tid < 24) *(uint4*)&s2h[0][s2w][s2part * 8] = *(const uint4*)s2src;
    __syncthreads();

    for (int jt = 0; jt < JCHUNK; jt += 64) {
        const int buf = (jt >> 6) & 1;

        // --- stage A: H tile load + half2 P-build into Ps[buf] ---
        {
            const uint4* src = (const uint4*)(hsrc + jt);
            *(uint4*)&Hs[buf][hcol][hpart * 16]     = src[0];
            *(uint4*)&Hs[buf][hcol][hpart * 16 + 8] = src[1];
        }
        unsigned pph[8];
#pragma unroll
        for (int hh = 0; hh < 2; hh++) {
            uint4 A2 = *(const uint4*)&s2h[buf][0][pj + hh * 8];
            uint4 EP = *(const uint4*)&s2h[buf][1][pj + hh * 8];
            uint4 EN = *(const uint4*)&s2h[buf][2][pj + hh * 8];
            unsigned a2w[4] = {A2.x, A2.y, A2.z, A2.w};
            unsigned epw[4] = {EP.x, EP.y, EP.z, EP.w};
            unsigned enw[4] = {EN.x, EN.y, EN.z, EN.w};
#pragma unroll
            for (int q2 = 0; q2 < 2; q2++) {
                float4 av = aregs[hh * 2 + q2];
#pragma unroll
                for (int sub = 0; sub < 2; sub++) {
                    const int k = q2 * 2 + sub;
                    unsigned adjw = h2u(sub == 0 ? __floats2half2_rn(av.x, av.y)
                                                 : __floats2half2_rn(av.z, av.w));
                    unsigned s = h2u(__hadd2(u2h(a1u), u2h(a2w[k])));
                    unsigned m = __hge2_mask(u2h(s), hzero);
                    unsigned f1 = (e1pu & m) | (e1nu & ~m);
                    unsigned f2 = (epw[k] & m) | (enw[k] & ~m);
                    pph[hh * 4 + k] =
                        h2u(__hmul2(__hmul2(u2h(f1), u2h(f2)), u2h(adjw)));
                }
            }
        }
        *(uint4*)&Ps[buf][pr][pj]     = make_uint4(pph[0], pph[1], pph[2], pph[3]);
        *(uint4*)&Ps[buf][pr][pj + 8] = make_uint4(pph[4], pph[5], pph[6], pph[7]);

        // --- prefetch tile t+1 (adj regs + s2 into other buffer) ---
        if (jt + 64 < JCHUNK) {
            const float* an = arow + jt + 64;
#pragma unroll
            for (int q = 0; q < 4; q++) aregs[q] = *(const float4*)(an + q * 4);
            if (tid < 24)
                *(uint4*)&s2h[buf ^ 1][s2w][s2part * 8] =
                    *(const uint4*)(s2src + jt + 64);
        }
        __syncthreads();

        // --- stage B: fp16 mma over Ps[buf] (A) x Hs[buf] (B) ---
#pragma unroll
        for (int kk = 0; kk < 4; kk++) {
            const int k0 = kk * 16;
            unsigned a0 = *(const unsigned*)&Ps[buf][wy * 16 + g][k0 + 2 * t4];
            unsigned a1 = *(const unsigned*)&Ps[buf][wy * 16 + g + 8][k0 + 2 * t4];
            unsigned a2 = *(const unsigned*)&Ps[buf][wy * 16 + g][k0 + 2 * t4 + 8];
            unsigned a3 = *(const unsigned*)&Ps[buf][wy * 16 + g + 8][k0 + 2 * t4 + 8];
            if (wx == 0) mma_f16(accD, a0, a1, a2, a3, ONEH2, ONEH2);
#pragma unroll
            for (int nf = 0; nf < 4; nf++) {
                const int n0 = wx * 32 + nf * 8;
                unsigned b0 = *(const unsigned*)&Hs[buf][n0 + g][k0 + 2 * t4];
                unsigned b1 = *(const unsigned*)&Hs[buf][n0 + g][k0 + 2 * t4 + 8];
                mma_f16(acc[nf], a0, a1, a2, a3, b0, b1);
            }
        }
    }

    // denominator: every column of accD equals the row sum
    if (wx == 0 && t4 == 0) {
        g_pden[split][row0 + wy * 16 + g]     = accD[0];
        g_pden[split][row0 + wy * 16 + g + 8] = accD[2];
    }

    // partial accumulator: c0,c1 = (row g, col 2t4,2t4+1); c2,c3 = row g+8
    float* pa = g_pacc[split];
#pragma unroll
    for (int nf = 0; nf < 4; nf++) {
        const int col = wx * 32 + nf * 8 + t4 * 2;
        const int r = row0 + wy * 16 + g;
        *(float2*)&pa[(size_t)r * FOUT + col]       = make_float2(acc[nf][0], acc[nf][1]);
        *(float2*)&pa[(size_t)(r + 8) * FOUT + col] = make_float2(acc[nf][2], acc[nf][3]);
    }
}

// ---------------------------------------------------------------------------
// K4: epilogue — merge split-j partials, normalize, ELU, write out.
// ---------------------------------------------------------------------------
__global__ __launch_bounds__(256) void k4_epi(float* __restrict__ out) {
    const int idx = blockIdx.x * 256 + threadIdx.x;
    const int row = idx >> 4;
    const int cg = (idx & 15) << 2;
    float4 v = make_float4(0.f, 0.f, 0.f, 0.f);
    float den = 0.f;
#pragma unroll
    for (int s = 0; s < JSPLIT; s++) {
        float4 p = *(const float4*)&g_pacc[s][(size_t)row * FOUT + cg];
        v.x += p.x; v.y += p.y; v.z += p.z; v.w += p.w;
        den += g_pden[s][row];
    }
    float inv = 1.f / den;
    float4 r;
    float t0 = v.x * inv; r.x = t0 > 0.f ? t0 : expm1f(t0);
    float t1 = v.y * inv; r.y = t1 > 0.f ? t1 : expm1f(t1);
    float t2 = v.z * inv; r.z = t2 > 0.f ? t2 : expm1f(t2);
    float t3 = v.w * inv; r.w = t3 > 0.f ? t3 : expm1f(t3);
    *(float4*)&out[(size_t)row * FOUT + cg] = r;
}

// ---------------------------------------------------------------------------
extern "C" void kernel_launch(void* const* d_in, const int* in_sizes, int n_in,
                              void* d_out, int out_size) {
    const float *x = nullptr, *adj = nullptr, *W = nullptr, *a = nullptr;
    for (int i = 0; i < n_in; i++) {
        switch (in_sizes[i]) {
            case NROWS * FIN:   x   = (const float*)d_in[i]; break;
            case NROWS * NROWS: adj = (const float*)d_in[i]; break;
            case FIN * FOUT:    W   = (const float*)d_in[i]; break;
            case 2 * FOUT:      a   = (const float*)d_in[i]; break;
        }
    }
    float* out = (float*)d_out;

    k1_gemm<<<NROWS / 64, 256>>>(x, W);
    k1t_trans<<<NROWS / 64, 256>>>();
    k2_att<<<NROWS / 8, 256>>>(a);
    k2bc_pre<<<NROWS / 256, 256>>>();
    dim3 g3(NROWS / 64, JSPLIT);
    k3_fused<<<g3, 256>>>(adj);
    k4_epi<<<NROWS * FOUT / 4 / 256, 256>>>(out);
}